// round 4
// baseline (speedup 1.0000x reference)
#include <cuda_runtime.h>

#define T_OLD 60000
#define T_NEW 60000
#define NV 30000
#define MAX_STEPS 300

#define THT_BITS 17
#define THT_SIZE (1 << THT_BITS)
#define FHT_BITS 19
#define FHT_SIZE (1 << FHT_BITS)

__device__ unsigned long long g_tkey[THT_SIZE];
__device__ unsigned int       g_tval[THT_SIZE];   // t+1, 0 = empty
__device__ unsigned long long g_fkey[FHT_SIZE];
__device__ unsigned int       g_fval[FHT_SIZE];   // pos+1 (pos = f*T_OLD+t), 0 = empty
__device__ int                g_nbr[T_OLD * 4];
__device__ unsigned int       g_prio[NV];
__device__ float              g_ocent[T_OLD * 3];
__device__ float              g_oel[T_OLD];
__device__ int                g_degen[T_OLD];
__device__ int                g_remap[T_NEW];
__device__ int                g_matched[T_NEW];
__device__ float              g_cent[T_NEW * 3];
__device__ int                g_needfb[T_NEW];
__device__ int                g_fbcount;
__device__ int                g_stride;           // 1 = int32 indices, 2 = int64 indices

__device__ __forceinline__ int clampi(int x, int lo, int hi) {
    return x < lo ? lo : (x > hi ? hi : x);
}
// load vertex index: works for int32 (stride 1) or little-endian int64 (stride 2,
// low word only — values < 2^31). Always in-bounds for either dtype. Clamped.
__device__ __forceinline__ int ldvi(const int* base, int idx, int stride) {
    int v = base[idx * stride];
    return clampi(v, 0, NV - 1);
}

__device__ __forceinline__ unsigned long long hash64(unsigned long long x) {
    x += 0x9E3779B97F4A7C15ull;
    x = (x ^ (x >> 30)) * 0xBF58476D1CE4E5B9ull;
    x = (x ^ (x >> 27)) * 0x94D049BB133111EBull;
    return x ^ (x >> 31);
}

__device__ __forceinline__ void sort4(int v[4]) {
    #define CSWP(a,b) { if (v[a] > v[b]) { int t = v[a]; v[a] = v[b]; v[b] = t; } }
    CSWP(0,1) CSWP(2,3) CSWP(0,2) CSWP(1,3) CSWP(1,2)
    #undef CSWP
}

// detect index dtype: int64 buffers have all-zero odd 32-bit words (values < 2^31)
__global__ void k_detect(const int* __restrict__ ni) {
    if (threadIdx.x == 0 && blockIdx.x == 0) {
        bool all_zero = true;
        for (int k = 1; k < 64; k += 2)
            if (ni[k] != 0) { all_zero = false; break; }
        g_stride = all_zero ? 2 : 1;
    }
}

__global__ void k_init() {
    int i = blockIdx.x * blockDim.x + threadIdx.x;
    int stride = gridDim.x * blockDim.x;
    for (int j = i; j < FHT_SIZE; j += stride) g_fval[j] = 0u;
    for (int j = i; j < THT_SIZE; j += stride) g_tval[j] = 0u;
    for (int j = i; j < T_OLD * 4; j += stride) g_nbr[j] = -1;
    for (int j = i; j < NV; j += stride) g_prio[j] = 0u;
    if (i == 0) g_fbcount = 0;
}

__global__ void k_old(const int* __restrict__ oi, const float* __restrict__ vp) {
    int t = blockIdx.x * blockDim.x + threadIdx.x;
    if (t >= T_OLD) return;
    int st = g_stride;

    int v[4];
    #pragma unroll
    for (int k = 0; k < 4; k++) v[k] = ldvi(oi, t * 4 + k, st);

    int s[4] = { v[0], v[1], v[2], v[3] };
    sort4(s);

    {
        unsigned long long key =
            ((((unsigned long long)s[0] * NV + (unsigned long long)s[1]) * NV
              + (unsigned long long)s[2]) * NV) + (unsigned long long)s[3];
        unsigned int slot = (unsigned int)(hash64(key) & (THT_SIZE - 1));
        while (true) {
            unsigned int prev = atomicCAS(&g_tval[slot], 0u, (unsigned int)(t + 1));
            if (prev == 0u) { g_tkey[slot] = key; break; }
            slot = (slot + 1) & (THT_SIZE - 1);
        }
    }

    #pragma unroll
    for (int vi = 0; vi < 4; vi++)
        atomicMax(&g_prio[v[vi]], (unsigned int)(vi * T_OLD + t + 1));

    float p[4][3];
    #pragma unroll
    for (int k = 0; k < 4; k++) {
        int b = v[k] * 3;
        p[k][0] = vp[b]; p[k][1] = vp[b + 1]; p[k][2] = vp[b + 2];
    }
    #pragma unroll
    for (int d = 0; d < 3; d++)
        g_ocent[t * 3 + d] = (p[0][d] + p[1][d] + p[2][d] + p[3][d]) * 0.25f;

    const int ea[6] = {0,0,0,1,1,2}, eb[6] = {1,2,3,2,3,3};
    float mel = 3.4e38f;
    #pragma unroll
    for (int e = 0; e < 6; e++) {
        float dx = p[ea[e]][0] - p[eb[e]][0];
        float dy = p[ea[e]][1] - p[eb[e]][1];
        float dz = p[ea[e]][2] - p[eb[e]][2];
        mel = fminf(mel, sqrtf(dx * dx + dy * dy + dz * dz));
    }
    g_oel[t] = mel;

    float e1x = p[1][0]-p[0][0], e1y = p[1][1]-p[0][1], e1z = p[1][2]-p[0][2];
    float e2x = p[2][0]-p[0][0], e2y = p[2][1]-p[0][1], e2z = p[2][2]-p[0][2];
    float e3x = p[3][0]-p[0][0], e3y = p[3][1]-p[0][1], e3z = p[3][2]-p[0][2];
    float det = e1x * (e2y * e3z - e2z * e3y)
              - e2x * (e1y * e3z - e1z * e3y)
              + e3x * (e1y * e2z - e1z * e2y);
    g_degen[t] = (fabsf(det) < 1e-10f) ? 1 : 0;

    #pragma unroll
    for (int f = 0; f < 4; f++) {
        int a[3];
        int w = 0;
        #pragma unroll
        for (int k = 0; k < 4; k++) if (k != f) a[w++] = v[k];
        unsigned long long fk =
            (((unsigned long long)a[0] * NV + (unsigned long long)a[1]) * NV)
            + (unsigned long long)a[2];
        unsigned int slot = (unsigned int)(hash64(fk) & (FHT_SIZE - 1));
        unsigned int pay = (unsigned int)(f * T_OLD + t + 1);
        while (true) {
            unsigned int prev = atomicCAS(&g_fval[slot], 0u, pay);
            if (prev == 0u) { g_fkey[slot] = fk; break; }
            slot = (slot + 1) & (FHT_SIZE - 1);
        }
    }
}

__global__ void k_pair(const int* __restrict__ oi) {
    int t = blockIdx.x * blockDim.x + threadIdx.x;
    if (t >= T_OLD) return;
    if (g_degen[t]) return;   // degen rows stay -1
    int st = g_stride;

    int v[4];
    #pragma unroll
    for (int k = 0; k < 4; k++) v[k] = ldvi(oi, t * 4 + k, st);

    #pragma unroll
    for (int f = 0; f < 4; f++) {
        int a[3];
        int w = 0;
        #pragma unroll
        for (int k = 0; k < 4; k++) if (k != f) a[w++] = v[k];
        unsigned long long fk =
            (((unsigned long long)a[0] * NV + (unsigned long long)a[1]) * NV)
            + (unsigned long long)a[2];
        int mypos = f * T_OLD + t;

        int m[8]; int cnt = 0;
        unsigned int slot = (unsigned int)(hash64(fk) & (FHT_SIZE - 1));
        while (true) {
            unsigned int val = g_fval[slot];
            if (val == 0u) break;
            if (g_fkey[slot] == fk) {
                if (cnt < 8) m[cnt] = (int)val - 1;
                cnt++;
            }
            slot = (slot + 1) & (FHT_SIZE - 1);
        }
        if (cnt < 2) continue;
        if (cnt > 8) cnt = 8;

        for (int x = 1; x < cnt; x++) {
            int key = m[x], y = x - 1;
            while (y >= 0 && m[y] > key) { m[y + 1] = m[y]; y--; }
            m[y + 1] = key;
        }
        int self = 0;
        for (int x = 0; x < cnt; x++) if (m[x] == mypos) { self = x; break; }
        int npos = (self > 0) ? m[self - 1] : m[1];
        g_nbr[t * 4 + f] = clampi(npos % T_OLD, 0, T_OLD - 1);
    }
}

__global__ void k_new(const int* __restrict__ ni, const int* __restrict__ oi,
                      const float* __restrict__ vp) {
    int i = blockIdx.x * blockDim.x + threadIdx.x;
    if (i >= T_NEW) return;
    int stq = g_stride;

    int n[4];
    #pragma unroll
    for (int k = 0; k < 4; k++) n[k] = ldvi(ni, i * 4 + k, stq);
    int s[4] = { n[0], n[1], n[2], n[3] };
    sort4(s);

    int matched = -1;
    {
        unsigned long long key =
            ((((unsigned long long)s[0] * NV + (unsigned long long)s[1]) * NV
              + (unsigned long long)s[2]) * NV) + (unsigned long long)s[3];
        unsigned int slot = (unsigned int)(hash64(key) & (THT_SIZE - 1));
        while (true) {
            unsigned int val = g_tval[slot];
            if (val == 0u) break;
            if (g_tkey[slot] == key) {
                int tt = (int)val - 1;
                if (tt > matched) matched = tt;
            }
            slot = (slot + 1) & (THT_SIZE - 1);
        }
    }
    matched = matched > T_OLD - 1 ? T_OLD - 1 : matched;
    g_matched[i] = matched;

    float cx = 0.f, cy = 0.f, cz = 0.f;
    #pragma unroll
    for (int k = 0; k < 4; k++) {
        int b = n[k] * 3;
        cx += vp[b]; cy += vp[b + 1]; cz += vp[b + 2];
    }
    cx *= 0.25f; cy *= 0.25f; cz *= 0.25f;
    g_cent[i * 3 + 0] = cx; g_cent[i * 3 + 1] = cy; g_cent[i * 3 + 2] = cz;

    unsigned int pv = g_prio[n[0]];
    int seed = (pv > 0u) ? (int)((pv - 1u) % T_OLD) : 0;

    if (matched >= 0) { g_remap[i] = seed; g_needfb[i] = 0; return; }

    int cur = seed;
    int rem = seed;
    int fb = 0;
    bool done = false;
    for (int step = 0; step < MAX_STEPS; step++) {
        int b0 = ldvi(oi, cur * 4 + 0, stq) * 3;
        int b1 = ldvi(oi, cur * 4 + 1, stq) * 3;
        int b2 = ldvi(oi, cur * 4 + 2, stq) * 3;
        int b3 = ldvi(oi, cur * 4 + 3, stq) * 3;
        float q0x=vp[b0], q0y=vp[b0+1], q0z=vp[b0+2];
        float q1x=vp[b1], q1y=vp[b1+1], q1z=vp[b1+2];
        float q2x=vp[b2], q2y=vp[b2+1], q2z=vp[b2+2];
        float q3x=vp[b3], q3y=vp[b3+1], q3z=vp[b3+2];

        float rx = cx - q0x, ry = cy - q0y, rz = cz - q0z;
        float b1v, b2v, b3v;
        if (g_degen[cur]) {
            b1v = rx; b2v = ry; b3v = rz;
        } else {
            float e1x=q1x-q0x, e1y=q1y-q0y, e1z=q1z-q0z;
            float e2x=q2x-q0x, e2y=q2y-q0y, e2z=q2z-q0z;
            float e3x=q3x-q0x, e3y=q3y-q0y, e3z=q3z-q0z;
            float c23x = e2y*e3z - e2z*e3y, c23y = e2z*e3x - e2x*e3z, c23z = e2x*e3y - e2y*e3x;
            float c31x = e3y*e1z - e3z*e1y, c31y = e3z*e1x - e3x*e1z, c31z = e3x*e1y - e3y*e1x;
            float c12x = e1y*e2z - e1z*e2y, c12y = e1z*e2x - e1x*e2z, c12z = e1x*e2y - e1y*e2x;
            float det = e1x * c23x + e1y * c23y + e1z * c23z;
            float inv = 1.0f / det;
            b1v = (rx * c23x + ry * c23y + rz * c23z) * inv;
            b2v = (rx * c31x + ry * c31y + rz * c31z) * inv;
            b3v = (rx * c12x + ry * c12y + rz * c12z) * inv;
        }
        float b0v = 1.0f - (b1v + b2v + b3v);
        float mn = fminf(fminf(b0v, b1v), fminf(b2v, b3v));
        if (mn >= -0.0001f) { rem = cur; done = true; break; }
        int arg = 0; float bv = b0v;
        if (b1v < bv) { bv = b1v; arg = 1; }
        if (b2v < bv) { bv = b2v; arg = 2; }
        if (b3v < bv) { bv = b3v; arg = 3; }
        int nb = g_nbr[cur * 4 + arg];
        if (nb < 0) { rem = cur; done = true; break; }
        cur = clampi(nb, 0, T_OLD - 1);
    }
    if (!done) { rem = cur; fb = 1; atomicAdd(&g_fbcount, 1); }
    g_remap[i] = rem;
    g_needfb[i] = fb;
}

__global__ void k_fb() {
    int i = blockIdx.x * blockDim.x + threadIdx.x;
    if (i >= T_NEW) return;
    if (g_fbcount == 0) return;
    if (!g_needfb[i]) return;
    float cx = g_cent[i*3], cy = g_cent[i*3+1], cz = g_cent[i*3+2];
    float p2 = cx*cx + cy*cy + cz*cz;
    float bd = 3.4e38f;
    int bi = 0;
    for (int j = 0; j < T_OLD; j++) {
        float ox = g_ocent[j*3], oy = g_ocent[j*3+1], oz = g_ocent[j*3+2];
        float d = p2 - 2.0f * (cx*ox + cy*oy + cz*oz) + (ox*ox + oy*oy + oz*oz);
        if (d < bd) { bd = d; bi = j; }
    }
    g_remap[i] = clampi(bi, 0, T_OLD - 1);
}

__global__ void k_final(const int* __restrict__ ni, const int* __restrict__ oi,
                        const float* __restrict__ occ, const float* __restrict__ ncc,
                        const float* __restrict__ vp, float* __restrict__ out,
                        int out_size) {
    int i = blockIdx.x * blockDim.x + threadIdx.x;
    if (i >= T_NEW) return;
    int stq = g_stride;

    int m = g_matched[i];
    int r = clampi(g_remap[i], 0, T_OLD - 1);
    int cand[5];
    if (m >= 0) {
        #pragma unroll
        for (int c = 0; c < 5; c++) cand[c] = m;
    } else {
        cand[0] = r;
        #pragma unroll
        for (int j = 0; j < 4; j++) {
            int nb = g_nbr[r * 4 + j];
            cand[1 + j] = (nb >= 0) ? clampi(nb, 0, T_OLD - 1) : r;
        }
    }

    int n[4];
    #pragma unroll
    for (int k = 0; k < 4; k++) n[k] = ldvi(ni, i * 4 + k, stq);

    float p[4][3];
    #pragma unroll
    for (int k = 0; k < 4; k++) {
        int b = n[k] * 3;
        p[k][0] = vp[b]; p[k][1] = vp[b+1]; p[k][2] = vp[b+2];
    }
    const int ea[6] = {0,0,0,1,1,2}, eb[6] = {1,2,3,2,3,3};
    float nel = 3.4e38f;
    #pragma unroll
    for (int e = 0; e < 6; e++) {
        float dx = p[ea[e]][0] - p[eb[e]][0];
        float dy = p[ea[e]][1] - p[eb[e]][1];
        float dz = p[ea[e]][2] - p[eb[e]][2];
        nel = fminf(nel, sqrtf(dx*dx + dy*dy + dz*dz));
    }
    float nel_d = fmaxf(nel, 1e-8f);

    float nc0 = ncc[i*3], nc1 = ncc[i*3+1], nc2 = ncc[i*3+2];

    float raw[5], dens[5];
    float rsum = 0.0f;
    #pragma unroll
    for (int c = 0; c < 5; c++) {
        int ct = cand[c];
        int ovl = 0;
        #pragma unroll
        for (int a = 0; a < 4; a++) {
            int w = ldvi(oi, ct * 4 + a, stq);
            bool eq = (w == n[0]) | (w == n[1]) | (w == n[2]) | (w == n[3]);
            ovl += eq ? 1 : 0;
        }
        float d0 = occ[ct*3]   - nc0;
        float d1 = occ[ct*3+1] - nc1;
        float d2 = occ[ct*3+2] - nc2;
        float cc2 = d0*d0 + d1*d1 + d2*d2;
        raw[c] = expf(2.0f * (float)ovl) / (cc2 + 1e-8f);
        rsum += raw[c];
        float ds = g_oel[ct] / nel_d;
        dens[c] = fminf(fmaxf(ds, 0.1f), 10.0f);
    }

    const int OFF_W = T_NEW * 5;
    const int OFF_D = T_NEW * 10;
    #pragma unroll
    for (int c = 0; c < 5; c++) {
        int i0 = i * 5 + c;
        if (i0 < out_size)         out[i0]         = (float)cand[c];
        if (OFF_W + i0 < out_size) out[OFF_W + i0] = raw[c] / rsum;
        if (OFF_D + i0 < out_size) out[OFF_D + i0] = dens[c];
    }
}

// ---------------- launch: identify inputs by element count ----------------
extern "C" void kernel_launch(void* const* d_in, const int* in_sizes, int n_in,
                              void* d_out, int out_size) {
    const int*   ni  = 0;   // new_indices  (240000 ints, first)
    const int*   oi  = 0;   // old_indices  (240000 ints, second)
    const float* occ = 0;   // old_cc       (180000 f32, first)
    const float* ncc = 0;   // new_cc       (180000 f32, second)
    const float* vp  = 0;   // vertex_positions (90000 f32)

    for (int k = 0; k < n_in; k++) {
        int sz = in_sizes[k];
        if (sz == T_NEW * 4) {
            if (!ni) ni = (const int*)d_in[k];
            else if (!oi) oi = (const int*)d_in[k];
        } else if (sz == T_OLD * 3) {
            if (!occ) occ = (const float*)d_in[k];
            else if (!ncc) ncc = (const float*)d_in[k];
        } else if (sz == NV * 3) {
            vp = (const float*)d_in[k];
        }
    }
    if (!ni || !oi || !occ || !ncc || !vp) {
        ni  = (const int*)d_in[0];
        oi  = (const int*)d_in[1];
        occ = (const float*)d_in[2];
        ncc = (const float*)d_in[3];
        vp  = (const float*)d_in[4];
    }
    float* out = (float*)d_out;

    k_detect<<<1, 32>>>(ni);
    k_init<<<512, 256>>>();
    k_old<<<(T_OLD + 255) / 256, 256>>>(oi, vp);
    k_pair<<<(T_OLD + 255) / 256, 256>>>(oi);
    k_new<<<(T_NEW + 255) / 256, 256>>>(ni, oi, vp);
    k_fb<<<(T_NEW + 255) / 256, 256>>>();
    k_final<<<(T_NEW + 255) / 256, 256>>>(ni, oi, occ, ncc, vp, out, out_size);
}

// round 5
// speedup vs baseline: 1.3333x; 1.3333x over previous
#include <cuda_runtime.h>

#define T_OLD 60000
#define T_NEW 60000
#define NV 30000
#define MAX_STEPS 300

#define THT_BITS 17
#define THT_SIZE (1 << THT_BITS)
#define FHT_BITS 19
#define FHT_SIZE (1 << FHT_BITS)
#define KEY_EMPTY 0xFFFFFFFFFFFFFFFFull
#define WLCAP 4096

// ---------------- device scratch ----------------
__device__ unsigned long long g_tkey[THT_SIZE];   // tet table keys (unique)
__device__ unsigned int       g_tval[THT_SIZE];   // max(t)+1 via atomicMax, 0 = none
__device__ unsigned long long g_fkey[FHT_SIZE];   // face table keys (unique)
__device__ unsigned int       g_fval[FHT_SIZE];   // claimer pos+1 (pos = f*T_OLD+t)
__device__ int                g_nbr[T_OLD * 4];   // neighbors, -1 = none
__device__ unsigned int       g_prio[NV];         // max(vi*T_OLD+t)+1, 0 = none
__device__ float              g_ocent[T_OLD * 3];
__device__ float              g_oel[T_OLD];
__device__ int                g_degen[T_OLD];
__device__ int                g_wlslot[WLCAP];    // duplicate-face worklist
__device__ int                g_wlpos[WLCAP];
__device__ int                g_wlcount;

__device__ __forceinline__ int clampi(int x, int lo, int hi) {
    return x < lo ? lo : (x > hi ? hi : x);
}
__device__ __forceinline__ int cvi(int v) { return clampi(v, 0, NV - 1); }

__device__ __forceinline__ unsigned long long hash64(unsigned long long x) {
    x += 0x9E3779B97F4A7C15ull;
    x = (x ^ (x >> 30)) * 0xBF58476D1CE4E5B9ull;
    x = (x ^ (x >> 27)) * 0x94D049BB133111EBull;
    return x ^ (x >> 31);
}

__device__ __forceinline__ void sort4(int v[4]) {
    #define CSWP(a,b) { if (v[a] > v[b]) { int t = v[a]; v[a] = v[b]; v[b] = t; } }
    CSWP(0,1) CSWP(2,3) CSWP(0,2) CSWP(1,3) CSWP(1,2)
    #undef CSWP
}

// ---------------- kernel 0: clear scratch ----------------
__global__ void k_init() {
    int i = blockIdx.x * blockDim.x + threadIdx.x;
    int stride = gridDim.x * blockDim.x;
    for (int j = i; j < FHT_SIZE; j += stride) g_fkey[j] = KEY_EMPTY;
    for (int j = i; j < THT_SIZE; j += stride) { g_tkey[j] = KEY_EMPTY; g_tval[j] = 0u; }
    for (int j = i; j < T_OLD * 4; j += stride) g_nbr[j] = -1;
    for (int j = i; j < NV; j += stride) g_prio[j] = 0u;
    if (i == 0) g_wlcount = 0;
}

// ---------------- kernel 1: per old tet ----------------
__global__ void k_old(const int* __restrict__ oi, const float* __restrict__ vp) {
    int t = blockIdx.x * blockDim.x + threadIdx.x;
    if (t >= T_OLD) return;

    int4 vi4 = ((const int4*)oi)[t];
    int v[4] = { cvi(vi4.x), cvi(vi4.y), cvi(vi4.z), cvi(vi4.w) };
    int s[4] = { v[0], v[1], v[2], v[3] };
    sort4(s);

    // tet-key insert (unique key slots, value = max tet index)
    {
        unsigned long long key =
            ((((unsigned long long)s[0] * NV + (unsigned long long)s[1]) * NV
              + (unsigned long long)s[2]) * NV) + (unsigned long long)s[3];
        unsigned int slot = (unsigned int)(hash64(key) & (THT_SIZE - 1));
        while (true) {
            unsigned long long old = atomicCAS(&g_tkey[slot], KEY_EMPTY, key);
            if (old == KEY_EMPTY || old == key) {
                atomicMax(&g_tval[slot], (unsigned int)(t + 1));
                break;
            }
            slot = (slot + 1) & (THT_SIZE - 1);
        }
    }

    // vertex priority
    #pragma unroll
    for (int k = 0; k < 4; k++)
        atomicMax(&g_prio[v[k]], (unsigned int)(k * T_OLD + t + 1));

    // geometry
    float p[4][3];
    #pragma unroll
    for (int k = 0; k < 4; k++) {
        int b = v[k] * 3;
        p[k][0] = vp[b]; p[k][1] = vp[b + 1]; p[k][2] = vp[b + 2];
    }
    #pragma unroll
    for (int d = 0; d < 3; d++)
        g_ocent[t * 3 + d] = (p[0][d] + p[1][d] + p[2][d] + p[3][d]) * 0.25f;

    const int ea[6] = {0,0,0,1,1,2}, eb[6] = {1,2,3,2,3,3};
    float mel = 3.4e38f;
    #pragma unroll
    for (int e = 0; e < 6; e++) {
        float dx = p[ea[e]][0] - p[eb[e]][0];
        float dy = p[ea[e]][1] - p[eb[e]][1];
        float dz = p[ea[e]][2] - p[eb[e]][2];
        mel = fminf(mel, sqrtf(dx * dx + dy * dy + dz * dz));
    }
    g_oel[t] = mel;

    float e1x = p[1][0]-p[0][0], e1y = p[1][1]-p[0][1], e1z = p[1][2]-p[0][2];
    float e2x = p[2][0]-p[0][0], e2y = p[2][1]-p[0][1], e2z = p[2][2]-p[0][2];
    float e3x = p[3][0]-p[0][0], e3y = p[3][1]-p[0][1], e3z = p[3][2]-p[0][2];
    float det = e1x * (e2y * e3z - e2z * e3y)
              - e2x * (e1y * e3z - e1z * e3y)
              + e3x * (e1y * e2z - e1z * e2y);
    g_degen[t] = (fabsf(det) < 1e-10f) ? 1 : 0;

    // face inserts: unique-key table; duplicate detected at insert -> worklist
    #pragma unroll
    for (int f = 0; f < 4; f++) {
        int a[3];
        int w = 0;
        #pragma unroll
        for (int k = 0; k < 4; k++) if (k != f) a[w++] = v[k]; // rows pre-sorted in input
        unsigned long long fk =
            (((unsigned long long)a[0] * NV + (unsigned long long)a[1]) * NV)
            + (unsigned long long)a[2];
        unsigned int slot = (unsigned int)(hash64(fk) & (FHT_SIZE - 1));
        int mypos = f * T_OLD + t;
        while (true) {
            unsigned long long old = atomicCAS(&g_fkey[slot], KEY_EMPTY, fk);
            if (old == KEY_EMPTY) { g_fval[slot] = (unsigned int)(mypos + 1); break; }
            if (old == fk) {
                int e = atomicAdd(&g_wlcount, 1);
                if (e < WLCAP) { g_wlslot[e] = (int)slot; g_wlpos[e] = mypos; }
                break;
            }
            slot = (slot + 1) & (FHT_SIZE - 1);
        }
    }
}

// ---------------- kernel 2: resolve duplicate faces (tiny worklist) ----------------
__global__ void k_wl() {
    int cnt = g_wlcount;
    if (cnt > WLCAP) cnt = WLCAP;
    for (int e = threadIdx.x; e < cnt; e += blockDim.x) {
        int s = g_wlslot[e];
        int m[10];
        int c = 0;
        m[c++] = (int)g_fval[s] - 1;              // claimer pos
        for (int x = 0; x < cnt; x++)
            if (g_wlslot[x] == s && c < 10) m[c++] = g_wlpos[x];
        // sort ascending
        for (int x = 1; x < c; x++) {
            int key = m[x], y = x - 1;
            while (y >= 0 && m[y] > key) { m[y + 1] = m[y]; y--; }
            m[y + 1] = key;
        }
        // reference rule: entry 0 -> m[1]; entry j>=1 -> m[j-1]; degen rows stay -1
        for (int j = 0; j < c; j++) {
            int pos = m[j];
            int t = pos % T_OLD, f = pos / T_OLD;
            if (g_degen[t]) continue;
            int npos = (j > 0) ? m[j - 1] : m[1];
            g_nbr[t * 4 + f] = npos % T_OLD;
        }
    }
}

// ---------------- kernel 3: match + walk + fallback + epilogue (fused) ----------------
__global__ void k_newfinal(const int* __restrict__ ni, const int* __restrict__ oi,
                           const float* __restrict__ occ, const float* __restrict__ ncc,
                           const float* __restrict__ vp, float* __restrict__ out,
                           int out_size) {
    int i = blockIdx.x * blockDim.x + threadIdx.x;
    if (i >= T_NEW) return;

    int4 ni4 = ((const int4*)ni)[i];
    int n[4] = { cvi(ni4.x), cvi(ni4.y), cvi(ni4.z), cvi(ni4.w) };
    int s[4] = { n[0], n[1], n[2], n[3] };
    sort4(s);

    // matched lookup
    int matched = -1;
    {
        unsigned long long key =
            ((((unsigned long long)s[0] * NV + (unsigned long long)s[1]) * NV
              + (unsigned long long)s[2]) * NV) + (unsigned long long)s[3];
        unsigned int slot = (unsigned int)(hash64(key) & (THT_SIZE - 1));
        while (true) {
            unsigned long long k = g_tkey[slot];
            if (k == KEY_EMPTY) break;
            if (k == key) { matched = (int)g_tval[slot] - 1; break; }
            slot = (slot + 1) & (THT_SIZE - 1);
        }
    }
    matched = matched > T_OLD - 1 ? T_OLD - 1 : matched;

    // new centroid + min edge length (verts loaded once)
    float p[4][3];
    #pragma unroll
    for (int k = 0; k < 4; k++) {
        int b = n[k] * 3;
        p[k][0] = vp[b]; p[k][1] = vp[b + 1]; p[k][2] = vp[b + 2];
    }
    float cx = (p[0][0] + p[1][0] + p[2][0] + p[3][0]) * 0.25f;
    float cy = (p[0][1] + p[1][1] + p[2][1] + p[3][1]) * 0.25f;
    float cz = (p[0][2] + p[1][2] + p[2][2] + p[3][2]) * 0.25f;

    const int ea[6] = {0,0,0,1,1,2}, eb[6] = {1,2,3,2,3,3};
    float nel = 3.4e38f;
    #pragma unroll
    for (int e = 0; e < 6; e++) {
        float dx = p[ea[e]][0] - p[eb[e]][0];
        float dy = p[ea[e]][1] - p[eb[e]][1];
        float dz = p[ea[e]][2] - p[eb[e]][2];
        nel = fminf(nel, sqrtf(dx * dx + dy * dy + dz * dz));
    }
    float nel_d = fmaxf(nel, 1e-8f);

    // candidates
    int cand[5];
    if (matched >= 0) {
        #pragma unroll
        for (int c = 0; c < 5; c++) cand[c] = matched;
    } else {
        // seed
        unsigned int pv = g_prio[n[0]];
        int cur = (pv > 0u) ? (int)((pv - 1u) % T_OLD) : 0;
        int rem = cur;
        bool exhausted = true;
        for (int step = 0; step < MAX_STEPS; step++) {
            const int* ov = oi + cur * 4;
            int b0 = cvi(ov[0]) * 3, b1 = cvi(ov[1]) * 3;
            int b2 = cvi(ov[2]) * 3, b3 = cvi(ov[3]) * 3;
            float q0x = vp[b0], q0y = vp[b0+1], q0z = vp[b0+2];
            float rx = cx - q0x, ry = cy - q0y, rz = cz - q0z;
            float b1v, b2v, b3v;
            if (g_degen[cur]) {
                b1v = rx; b2v = ry; b3v = rz;   // Tinv = I
            } else {
                float e1x = vp[b1]-q0x, e1y = vp[b1+1]-q0y, e1z = vp[b1+2]-q0z;
                float e2x = vp[b2]-q0x, e2y = vp[b2+1]-q0y, e2z = vp[b2+2]-q0z;
                float e3x = vp[b3]-q0x, e3y = vp[b3+1]-q0y, e3z = vp[b3+2]-q0z;
                float c23x = e2y*e3z - e2z*e3y, c23y = e2z*e3x - e2x*e3z, c23z = e2x*e3y - e2y*e3x;
                float c31x = e3y*e1z - e3z*e1y, c31y = e3z*e1x - e3x*e1z, c31z = e3x*e1y - e3y*e1x;
                float c12x = e1y*e2z - e1z*e2y, c12y = e1z*e2x - e1x*e2z, c12z = e1x*e2y - e1y*e2x;
                float det = e1x * c23x + e1y * c23y + e1z * c23z;
                float inv = 1.0f / det;
                b1v = (rx * c23x + ry * c23y + rz * c23z) * inv;
                b2v = (rx * c31x + ry * c31y + rz * c31z) * inv;
                b3v = (rx * c12x + ry * c12y + rz * c12z) * inv;
            }
            float b0v = 1.0f - (b1v + b2v + b3v);
            float mn = fminf(fminf(b0v, b1v), fminf(b2v, b3v));
            if (mn >= -0.0001f) { rem = cur; exhausted = false; break; }
            int arg = 0; float bv = b0v;
            if (b1v < bv) { bv = b1v; arg = 1; }
            if (b2v < bv) { bv = b2v; arg = 2; }
            if (b3v < bv) { bv = b3v; arg = 3; }
            int nb = g_nbr[cur * 4 + arg];
            if (nb < 0) { rem = cur; exhausted = false; break; }
            cur = clampi(nb, 0, T_OLD - 1);
        }
        if (exhausted) {
            // per-thread nearest-centroid fallback (essentially never taken)
            float p2 = cx*cx + cy*cy + cz*cz;
            float bd = 3.4e38f;
            int bi = 0;
            for (int j = 0; j < T_OLD; j++) {
                float ox = g_ocent[j*3], oy = g_ocent[j*3+1], oz = g_ocent[j*3+2];
                float d = p2 - 2.0f * (cx*ox + cy*oy + cz*oz) + (ox*ox + oy*oy + oz*oz);
                if (d < bd) { bd = d; bi = j; }
            }
            rem = bi;
        }
        rem = clampi(rem, 0, T_OLD - 1);
        cand[0] = rem;
        #pragma unroll
        for (int j = 0; j < 4; j++) {
            int nb = g_nbr[rem * 4 + j];
            cand[1 + j] = (nb >= 0) ? clampi(nb, 0, T_OLD - 1) : rem;
        }
    }

    // epilogue
    float nc0 = ncc[i*3], nc1 = ncc[i*3+1], nc2 = ncc[i*3+2];
    float raw[5], dens[5];
    float rsum = 0.0f;
    #pragma unroll
    for (int c = 0; c < 5; c++) {
        int ct = cand[c];
        int4 ov4 = ((const int4*)oi)[ct];
        int w0 = cvi(ov4.x), w1 = cvi(ov4.y), w2 = cvi(ov4.z), w3 = cvi(ov4.w);
        int ovl = 0;
        #pragma unroll
        for (int a = 0; a < 4; a++) {
            int w = a == 0 ? w0 : a == 1 ? w1 : a == 2 ? w2 : w3;
            bool eq = (w == n[0]) | (w == n[1]) | (w == n[2]) | (w == n[3]);
            ovl += eq ? 1 : 0;
        }
        float d0 = occ[ct*3]   - nc0;
        float d1 = occ[ct*3+1] - nc1;
        float d2 = occ[ct*3+2] - nc2;
        float cc2 = d0*d0 + d1*d1 + d2*d2;
        raw[c] = expf(2.0f * (float)ovl) / (cc2 + 1e-8f);
        rsum += raw[c];
        float ds = g_oel[ct] / nel_d;
        dens[c] = fminf(fmaxf(ds, 0.1f), 10.0f);
    }

    const int OFF_W = T_NEW * 5;
    const int OFF_D = T_NEW * 10;
    #pragma unroll
    for (int c = 0; c < 5; c++) {
        int i0 = i * 5 + c;
        if (i0 < out_size)         out[i0]         = (float)cand[c];
        if (OFF_W + i0 < out_size) out[OFF_W + i0] = raw[c] / rsum;
        if (OFF_D + i0 < out_size) out[OFF_D + i0] = dens[c];
    }
}

// ---------------- launch ----------------
extern "C" void kernel_launch(void* const* d_in, const int* in_sizes, int n_in,
                              void* d_out, int out_size) {
    const int*   ni  = 0;
    const int*   oi  = 0;
    const float* occ = 0;
    const float* ncc = 0;
    const float* vp  = 0;

    for (int k = 0; k < n_in; k++) {
        int sz = in_sizes[k];
        if (sz == T_NEW * 4) {
            if (!ni) ni = (const int*)d_in[k];
            else if (!oi) oi = (const int*)d_in[k];
        } else if (sz == T_OLD * 3) {
            if (!occ) occ = (const float*)d_in[k];
            else if (!ncc) ncc = (const float*)d_in[k];
        } else if (sz == NV * 3) {
            vp = (const float*)d_in[k];
        }
    }
    if (!ni || !oi || !occ || !ncc || !vp) {
        ni  = (const int*)d_in[0];
        oi  = (const int*)d_in[1];
        occ = (const float*)d_in[2];
        ncc = (const float*)d_in[3];
        vp  = (const float*)d_in[4];
    }
    float* out = (float*)d_out;

    k_init<<<592, 256>>>();
    k_old<<<(T_OLD + 255) / 256, 256>>>(oi, vp);
    k_wl<<<1, 256>>>();
    k_newfinal<<<(T_NEW + 255) / 256, 256>>>(ni, oi, occ, ncc, vp, out, out_size);
}